// round 2
// baseline (speedup 1.0000x reference)
#include <cuda_runtime.h>
#include <cstdint>

#define N_NODES 100000
#define N_EDGES 1600000
#define DIM 128

// Scratch as float4 arrays: guarantees 16B alignment for vector ld/st/red.
__device__ float4 g_msg[(size_t)N_NODES * DIM / 4];
__device__ float4 g_h0 [(size_t)N_NODES * DIM / 4];
__device__ float4 g_h1 [(size_t)N_NODES * DIM / 4];
__device__ int    g_mode;   // 0 = int32, 1 = int64, 2 = float32 edge_index

// ---------------------------------------------------------------------------
// detect edge_index dtype. Reads only the first 32 entries of the src row,
// which is in-bounds under every candidate interpretation.
// ---------------------------------------------------------------------------
__global__ void detect_kernel(const void* eiv) {
    if (threadIdx.x != 0 || blockIdx.x != 0) return;
    const long long* e64 = (const long long*)eiv;
    const int*       e32 = (const int*)eiv;
    const float*     ef  = (const float*)eiv;
    bool ok64 = true, ok32 = true, okf = true;
    for (int i = 0; i < 32; i++) {
        long long v = e64[i];
        if (v < 0 || v >= N_NODES) ok64 = false;
        int w = e32[i];
        if (w < 0 || w >= N_NODES) ok32 = false;
        float f = ef[i];
        if (!(f >= 0.f && f < (float)N_NODES)) okf = false;
    }
    g_mode = ok64 ? 1 : (ok32 ? 0 : (okf ? 2 : 0));
}

// ---------------------------------------------------------------------------
// zero msg buffer
// ---------------------------------------------------------------------------
__global__ void zero_kernel(float4* __restrict__ p, int n4) {
    int i = blockIdx.x * blockDim.x + threadIdx.x;
    if (i < n4) p[i] = make_float4(0.f, 0.f, 0.f, 0.f);
}

// ---------------------------------------------------------------------------
// scatter-sum: one warp per edge, lane handles 4 channels, vector RED to L2
// ---------------------------------------------------------------------------
__global__ void scatter_kernel(const float4* __restrict__ e4,
                               const void* __restrict__ eiv,
                               float4* __restrict__ msg) {
    __shared__ int mode;
    if (threadIdx.x == 0) mode = g_mode;
    __syncthreads();
    int warp = (blockIdx.x * blockDim.x + threadIdx.x) >> 5;
    int lane = threadIdx.x & 31;
    if (warp >= N_EDGES) return;
    int d;
    if (mode == 1)      d = (int)((const long long*)eiv)[N_EDGES + warp];
    else if (mode == 0) d = ((const int*)eiv)[N_EDGES + warp];
    else                d = (int)((const float*)eiv)[N_EDGES + warp];
    d = min(max(d, 0), N_NODES - 1);   // defensive: never crash
    float4 v = e4[(size_t)warp * 32 + lane];
    float4* p = &msg[(size_t)d * 32 + lane];
    asm volatile("red.global.add.v4.f32 [%0], {%1,%2,%3,%4};"
                 :: "l"(p), "f"(v.x), "f"(v.y), "f"(v.z), "f"(v.w) : "memory");
}

// ---------------------------------------------------------------------------
// fp32 GEMM with packed f32x2 FMAs.
// out[r][c] = act( sum_k A[r][k] * W[k][c] + bias[c] )
// BM=64 rows per block, BN=128 (full width), 256 threads, 4x8 outputs/thread.
// ---------------------------------------------------------------------------
union F2 { float2 f; unsigned long long u; };

__device__ __forceinline__ void ffma2(F2& d, F2 a, F2 b) {
    asm("fma.rn.f32x2 %0, %1, %2, %0;" : "+l"(d.u) : "l"(a.u), "l"(b.u));
}

template<int K, bool RELU, bool CONCAT>
__global__ void __launch_bounds__(256, 1)
gemm_kernel(const float* __restrict__ A1, const float* __restrict__ A2,
            const float* __restrict__ W, const float* __restrict__ bias,
            float* __restrict__ out, int nrows) {
    constexpr int BM = 64, BN = 128, PAD = 4;
    constexpr int KQ = K / 4;          // float4 per logical A row
    extern __shared__ float smem[];
    float* Ws = smem;                  // [K][BN]
    float* As = smem + K * BN;         // [BM][K+PAD]

    const int tid = threadIdx.x;       // 256
    const int tx = tid & 15;           // column group: cols tx*8 .. tx*8+7
    const int ty = tid >> 4;           // row group:    rows ty*4 .. ty*4+3
    const int row0 = blockIdx.x * BM;

    // stage W (K*128 floats) via float4
    {
        const float4* W4 = (const float4*)W;
        float4* Ws4 = (float4*)Ws;
        #pragma unroll 4
        for (int i = tid; i < K * BN / 4; i += 256) Ws4[i] = W4[i];
    }
    // stage A tile (with optional concat of two 128-wide sources)
    for (int i = tid; i < BM * KQ; i += 256) {
        int r = i / KQ, kq = i % KQ;
        int row = row0 + r;
        if (row >= nrows) row = nrows - 1;   // clamp (outputs guarded later)
        float4 v;
        if (CONCAT) {
            if (kq < KQ / 2) v = ((const float4*)A1)[(size_t)row * (KQ / 2) + kq];
            else             v = ((const float4*)A2)[(size_t)row * (KQ / 2) + (kq - KQ / 2)];
        } else {
            v = ((const float4*)A1)[(size_t)row * KQ + kq];
        }
        *(float4*)&As[r * (K + PAD) + kq * 4] = v;
    }
    __syncthreads();

    F2 acc[4][4];
    #pragma unroll
    for (int i = 0; i < 4; i++)
        #pragma unroll
        for (int j = 0; j < 4; j++) acc[i][j].f = make_float2(0.f, 0.f);

    const float* wrow = &Ws[tx * 8];
    const float* arow = &As[ty * 4 * (K + PAD)];

    #pragma unroll 4
    for (int k = 0; k < K; k++) {
        float4 wlo = *(const float4*)&wrow[k * BN];
        float4 whi = *(const float4*)&wrow[k * BN + 4];
        F2 w0, w1, w2, w3;
        w0.f = make_float2(wlo.x, wlo.y);
        w1.f = make_float2(wlo.z, wlo.w);
        w2.f = make_float2(whi.x, whi.y);
        w3.f = make_float2(whi.z, whi.w);
        #pragma unroll
        for (int i = 0; i < 4; i++) {
            float a = arow[i * (K + PAD) + k];
            F2 aa; aa.f = make_float2(a, a);
            ffma2(acc[i][0], aa, w0);
            ffma2(acc[i][1], aa, w1);
            ffma2(acc[i][2], aa, w2);
            ffma2(acc[i][3], aa, w3);
        }
    }

    // epilogue: bias (+ relu), store
    float b[8];
    #pragma unroll
    for (int j = 0; j < 8; j++) b[j] = __ldg(&bias[tx * 8 + j]);

    #pragma unroll
    for (int i = 0; i < 4; i++) {
        int row = row0 + ty * 4 + i;
        if (row >= nrows) continue;
        float o[8];
        o[0] = acc[i][0].f.x + b[0]; o[1] = acc[i][0].f.y + b[1];
        o[2] = acc[i][1].f.x + b[2]; o[3] = acc[i][1].f.y + b[3];
        o[4] = acc[i][2].f.x + b[4]; o[5] = acc[i][2].f.y + b[5];
        o[6] = acc[i][3].f.x + b[6]; o[7] = acc[i][3].f.y + b[7];
        if (RELU) {
            #pragma unroll
            for (int j = 0; j < 8; j++) o[j] = fmaxf(o[j], 0.f);
        }
        float4 v0 = make_float4(o[0], o[1], o[2], o[3]);
        float4 v1 = make_float4(o[4], o[5], o[6], o[7]);
        float4* dst = (float4*)&out[(size_t)row * BN + tx * 8];
        dst[0] = v0; dst[1] = v1;
    }
}

// ---------------------------------------------------------------------------
// GroupNorm(1 group) + residual: one warp per row
// ---------------------------------------------------------------------------
__global__ void norm_kernel(const float4* __restrict__ h, const float4* __restrict__ x,
                            const float4* __restrict__ gw, const float4* __restrict__ gb,
                            float4* __restrict__ out) {
    int row = blockIdx.x * 8 + (threadIdx.x >> 5);
    int lane = threadIdx.x & 31;
    if (row >= N_NODES) return;
    float4 v = h[(size_t)row * 32 + lane];
    float s  = v.x + v.y + v.z + v.w;
    float ss = v.x * v.x + v.y * v.y + v.z * v.z + v.w * v.w;
    #pragma unroll
    for (int o = 16; o; o >>= 1) {
        s  += __shfl_xor_sync(0xFFFFFFFFu, s,  o);
        ss += __shfl_xor_sync(0xFFFFFFFFu, ss, o);
    }
    float mu  = s * (1.f / 128.f);
    float var = ss * (1.f / 128.f) - mu * mu;
    float rs  = rsqrtf(var + 1e-5f);
    float4 xg = x[(size_t)row * 32 + lane];
    float4 w4 = gw[lane];
    float4 b4 = gb[lane];
    float4 o4;
    o4.x = xg.x + (v.x - mu) * rs * w4.x + b4.x;
    o4.y = xg.y + (v.y - mu) * rs * w4.y + b4.y;
    o4.z = xg.z + (v.z - mu) * rs * w4.z + b4.z;
    o4.w = xg.w + (v.w - mu) * rs * w4.w + b4.w;
    out[(size_t)row * 32 + lane] = o4;
}

// ---------------------------------------------------------------------------
// launch
// ---------------------------------------------------------------------------
extern "C" void kernel_launch(void* const* d_in, const int* in_sizes, int n_in,
                              void* d_out, int out_size) {
    const float* x  = (const float*)d_in[0];
    const float* e  = (const float*)d_in[1];
    const void*  ei = d_in[2];
    const float* W0 = (const float*)d_in[3];
    const float* b0 = (const float*)d_in[4];
    const float* Wh = (const float*)d_in[5];
    const float* bh = (const float*)d_in[6];
    const float* Wo = (const float*)d_in[7];
    const float* bo = (const float*)d_in[8];
    const float* gw = (const float*)d_in[9];
    const float* gb = (const float*)d_in[10];
    float4* out = (float4*)d_out;

    float4 *msg, *h0, *h1;
    cudaGetSymbolAddress((void**)&msg, g_msg);
    cudaGetSymbolAddress((void**)&h0,  g_h0);
    cudaGetSymbolAddress((void**)&h1,  g_h1);

    const int smem0 = (256 * 128 + 64 * (256 + 4)) * 4;  // 197632 B
    const int smemH = (128 * 128 + 64 * (128 + 4)) * 4;  //  99328 B
    cudaFuncSetAttribute(gemm_kernel<256, true,  true >, cudaFuncAttributeMaxDynamicSharedMemorySize, smem0);
    cudaFuncSetAttribute(gemm_kernel<128, true,  false>, cudaFuncAttributeMaxDynamicSharedMemorySize, smemH);
    cudaFuncSetAttribute(gemm_kernel<128, false, false>, cudaFuncAttributeMaxDynamicSharedMemorySize, smemH);

    // 0) detect edge_index dtype
    detect_kernel<<<1, 32>>>(ei);
    // 1) zero msg
    zero_kernel<<<(N_NODES * DIM / 4 + 255) / 256, 256>>>(msg, N_NODES * DIM / 4);
    // 2) scatter-sum edges -> msg (dst row at offset N_EDGES)
    scatter_kernel<<<N_EDGES / 8, 256>>>((const float4*)e, ei, msg);

    const int gblocks = (N_NODES + 63) / 64;
    // 3) layer 0: relu([x, msg] @ W0 + b0)
    gemm_kernel<256, true, true ><<<gblocks, 256, smem0>>>(x, (const float*)msg, W0, b0, (float*)h0, N_NODES);
    // 4) hidden layers
    gemm_kernel<128, true, false><<<gblocks, 256, smemH>>>((const float*)h0, nullptr, Wh,             bh,       (float*)h1, N_NODES);
    gemm_kernel<128, true, false><<<gblocks, 256, smemH>>>((const float*)h1, nullptr, Wh + 128 * 128, bh + 128, (float*)h0, N_NODES);
    // 5) output layer (no relu)
    gemm_kernel<128, false, false><<<gblocks, 256, smemH>>>((const float*)h0, nullptr, Wo, bo, (float*)h1, N_NODES);
    // 6) groupnorm + residual
    norm_kernel<<<(N_NODES + 7) / 8, 256>>>(h1, (const float4*)x, (const float4*)gw, (const float4*)gb, out);
}

// round 3
// speedup vs baseline: 1.4254x; 1.4254x over previous
#include <cuda_runtime.h>
#include <cstdint>

#define N_NODES 100000
#define N_EDGES 1600000
#define DIM 128

// Scratch as float4 arrays: guarantees 16B alignment for vector ld/st/red.
__device__ float4 g_msg[(size_t)N_NODES * DIM / 4];
__device__ float4 g_h0 [(size_t)N_NODES * DIM / 4];
__device__ float4 g_h1 [(size_t)N_NODES * DIM / 4];
__device__ int    g_mode;   // 0 = int32, 1 = int64, 2 = float32 edge_index

// ---------------------------------------------------------------------------
// detect edge_index dtype (reads only first 32 src entries — always in bounds)
// ---------------------------------------------------------------------------
__global__ void detect_kernel(const void* eiv) {
    if (threadIdx.x != 0 || blockIdx.x != 0) return;
    const long long* e64 = (const long long*)eiv;
    const int*       e32 = (const int*)eiv;
    const float*     ef  = (const float*)eiv;
    bool ok64 = true, ok32 = true, okf = true;
    for (int i = 0; i < 32; i++) {
        long long v = e64[i];
        if (v < 0 || v >= N_NODES) ok64 = false;
        int w = e32[i];
        if (w < 0 || w >= N_NODES) ok32 = false;
        float f = ef[i];
        if (!(f >= 0.f && f < (float)N_NODES)) okf = false;
    }
    g_mode = ok64 ? 1 : (ok32 ? 0 : (okf ? 2 : 0));
}

// ---------------------------------------------------------------------------
// zero msg buffer
// ---------------------------------------------------------------------------
__global__ void zero_kernel(float4* __restrict__ p, int n4) {
    int i = blockIdx.x * blockDim.x + threadIdx.x;
    if (i < n4) p[i] = make_float4(0.f, 0.f, 0.f, 0.f);
}

// ---------------------------------------------------------------------------
// scatter-sum: one warp per edge, lane handles 4 channels, vector RED to L2
// ---------------------------------------------------------------------------
__global__ void scatter_kernel(const float4* __restrict__ e4,
                               const void* __restrict__ eiv,
                               float4* __restrict__ msg) {
    __shared__ int mode;
    if (threadIdx.x == 0) mode = g_mode;
    __syncthreads();
    int warp = (blockIdx.x * blockDim.x + threadIdx.x) >> 5;
    int lane = threadIdx.x & 31;
    if (warp >= N_EDGES) return;
    int d;
    if (mode == 1)      d = (int)((const long long*)eiv)[N_EDGES + warp];
    else if (mode == 0) d = ((const int*)eiv)[N_EDGES + warp];
    else                d = (int)((const float*)eiv)[N_EDGES + warp];
    d = min(max(d, 0), N_NODES - 1);   // defensive: never crash
    float4 v = e4[(size_t)warp * 32 + lane];
    float4* p = &msg[(size_t)d * 32 + lane];
    asm volatile("red.global.add.v4.f32 [%0], {%1,%2,%3,%4};"
                 :: "l"(p), "f"(v.x), "f"(v.y), "f"(v.z), "f"(v.w) : "memory");
}

// ---------------------------------------------------------------------------
// fp32 GEMM v2: 512 threads, BM=128, BN=128, 4 rows x 8 cols per thread.
// Column set per thread: {4tx..4tx+3, 64+4tx..64+4tx+3} -> conflict-free
// LDS.128 on W. A read as LDS.32 broadcasts. Register double-buffering.
// Optional fused GroupNorm(1)+residual epilogue (NORM).
// ---------------------------------------------------------------------------
union F2 { float2 f; unsigned long long u; };

__device__ __forceinline__ void ffma2(F2& d, F2 a, F2 b) {
    asm("fma.rn.f32x2 %0, %1, %2, %0;" : "+l"(d.u) : "l"(a.u), "l"(b.u));
}

template<int NCHUNK, bool RELU, bool NORM>
__global__ void __launch_bounds__(512, 1)
gemm2_kernel(const float* __restrict__ A1, const float* __restrict__ A2,
             const float* __restrict__ W, const float* __restrict__ bias,
             const float* __restrict__ xres, const float* __restrict__ gw,
             const float* __restrict__ gb,
             float* __restrict__ out, int nrows) {
    // smem: Ws[129][128], As[129][128]  (row 128 is a pad row for prefetch)
    extern __shared__ float sm[];
    float* Ws = sm;
    float* As = sm + 129 * 128;

    const int tid = threadIdx.x;           // 512
    const int tx = tid & 15;               // 16 column groups
    const int ty = tid >> 4;               // 32 row groups (4 rows each)
    const int row0 = blockIdx.x * 128;
    const int j0 = 4 * tx;                 // cols j0..j0+3
    const int j1 = 64 + 4 * tx;            // cols j1..j1+3

    F2 acc[4][4];
    #pragma unroll
    for (int i = 0; i < 4; i++)
        #pragma unroll
        for (int j = 0; j < 4; j++) acc[i][j].f = make_float2(0.f, 0.f);

    const int rbase = ty * 4;              // local row base

    #pragma unroll
    for (int c = 0; c < NCHUNK; c++) {
        const float* src = (c == 0) ? A1 : A2;
        const float4* W4 = (const float4*)(W + c * 128 * 128);
        // stage W chunk [128][128] — coalesced, conflict-free
        #pragma unroll
        for (int it = 0; it < 8; it++) {
            int i = tid + it * 512;
            int r = i >> 5, kq = i & 31;
            ((float4*)&Ws[r * 128])[kq] = W4[i];
        }
        // stage A tile [128 rows][128 k] — coalesced, conflict-free
        #pragma unroll
        for (int it = 0; it < 8; it++) {
            int i = tid + it * 512;
            int r = i >> 5, kq = i & 31;
            int row = row0 + r;
            if (row >= nrows) row = nrows - 1;   // clamp (stores guarded)
            ((float4*)&As[r * 128])[kq] = ((const float4*)src)[(size_t)row * 32 + kq];
        }
        __syncthreads();

        // main loop, register double-buffered, 2 k per iteration
        float4 wa0 = *(const float4*)&Ws[j0];
        float4 wa1 = *(const float4*)&Ws[j1];
        float a0[4], a1[4];
        #pragma unroll
        for (int i = 0; i < 4; i++) a0[i] = As[(rbase + i) * 128];

        #pragma unroll 8
        for (int k = 0; k < 128; k += 2) {
            // prefetch k+1
            float4 wb0 = *(const float4*)&Ws[(k + 1) * 128 + j0];
            float4 wb1 = *(const float4*)&Ws[(k + 1) * 128 + j1];
            #pragma unroll
            for (int i = 0; i < 4; i++) a1[i] = As[(rbase + i) * 128 + k + 1];
            // fma k
            {
                F2 w0, w1, w2, w3;
                w0.f = make_float2(wa0.x, wa0.y); w1.f = make_float2(wa0.z, wa0.w);
                w2.f = make_float2(wa1.x, wa1.y); w3.f = make_float2(wa1.z, wa1.w);
                #pragma unroll
                for (int i = 0; i < 4; i++) {
                    F2 aa; aa.f = make_float2(a0[i], a0[i]);
                    ffma2(acc[i][0], aa, w0); ffma2(acc[i][1], aa, w1);
                    ffma2(acc[i][2], aa, w2); ffma2(acc[i][3], aa, w3);
                }
            }
            // prefetch k+2 (k=126 reads pad row 128 — never used)
            wa0 = *(const float4*)&Ws[(k + 2) * 128 + j0];
            wa1 = *(const float4*)&Ws[(k + 2) * 128 + j1];
            #pragma unroll
            for (int i = 0; i < 4; i++) a0[i] = As[(rbase + i) * 128 + k + 2];
            // fma k+1
            {
                F2 w0, w1, w2, w3;
                w0.f = make_float2(wb0.x, wb0.y); w1.f = make_float2(wb0.z, wb0.w);
                w2.f = make_float2(wb1.x, wb1.y); w3.f = make_float2(wb1.z, wb1.w);
                #pragma unroll
                for (int i = 0; i < 4; i++) {
                    F2 aa; aa.f = make_float2(a1[i], a1[i]);
                    ffma2(acc[i][0], aa, w0); ffma2(acc[i][1], aa, w1);
                    ffma2(acc[i][2], aa, w2); ffma2(acc[i][3], aa, w3);
                }
            }
        }
        if (c + 1 < NCHUNK) __syncthreads();
    }

    // epilogue
    float4 b0v = __ldg((const float4*)bias + tx);
    float4 b1v = __ldg((const float4*)bias + 16 + tx);

    float4 gw0, gw1, gb0, gb1;
    if (NORM) {
        gw0 = __ldg((const float4*)gw + tx);      gw1 = __ldg((const float4*)gw + 16 + tx);
        gb0 = __ldg((const float4*)gb + tx);      gb1 = __ldg((const float4*)gb + 16 + tx);
    }

    #pragma unroll
    for (int i = 0; i < 4; i++) {
        int row = row0 + rbase + i;
        float o[8];
        o[0] = acc[i][0].f.x + b0v.x; o[1] = acc[i][0].f.y + b0v.y;
        o[2] = acc[i][1].f.x + b0v.z; o[3] = acc[i][1].f.y + b0v.w;
        o[4] = acc[i][2].f.x + b1v.x; o[5] = acc[i][2].f.y + b1v.y;
        o[6] = acc[i][3].f.x + b1v.z; o[7] = acc[i][3].f.y + b1v.w;
        if (RELU) {
            #pragma unroll
            for (int j = 0; j < 8; j++) o[j] = fmaxf(o[j], 0.f);
        }
        if (NORM) {
            // row is spread over 16 lanes (same ty): reduce with xor shuffles 1..8
            float s = 0.f, ss = 0.f;
            #pragma unroll
            for (int j = 0; j < 8; j++) { s += o[j]; ss += o[j] * o[j]; }
            #pragma unroll
            for (int off = 8; off; off >>= 1) {
                s  += __shfl_xor_sync(0xFFFFFFFFu, s,  off);
                ss += __shfl_xor_sync(0xFFFFFFFFu, ss, off);
            }
            float mu  = s * (1.f / 128.f);
            float var = ss * (1.f / 128.f) - mu * mu;
            float rs  = rsqrtf(var + 1e-5f);
            if (row < nrows) {
                float4 x0 = ((const float4*)xres)[(size_t)row * 32 + tx];
                float4 x1 = ((const float4*)xres)[(size_t)row * 32 + 16 + tx];
                float4 v0, v1;
                v0.x = x0.x + (o[0] - mu) * rs * gw0.x + gb0.x;
                v0.y = x0.y + (o[1] - mu) * rs * gw0.y + gb0.y;
                v0.z = x0.z + (o[2] - mu) * rs * gw0.z + gb0.z;
                v0.w = x0.w + (o[3] - mu) * rs * gw0.w + gb0.w;
                v1.x = x1.x + (o[4] - mu) * rs * gw1.x + gb1.x;
                v1.y = x1.y + (o[5] - mu) * rs * gw1.y + gb1.y;
                v1.z = x1.z + (o[6] - mu) * rs * gw1.z + gb1.z;
                v1.w = x1.w + (o[7] - mu) * rs * gw1.w + gb1.w;
                ((float4*)out)[(size_t)row * 32 + tx]      = v0;
                ((float4*)out)[(size_t)row * 32 + 16 + tx] = v1;
            }
        } else if (row < nrows) {
            float4 v0 = make_float4(o[0], o[1], o[2], o[3]);
            float4 v1 = make_float4(o[4], o[5], o[6], o[7]);
            ((float4*)out)[(size_t)row * 32 + tx]      = v0;
            ((float4*)out)[(size_t)row * 32 + 16 + tx] = v1;
        }
    }
}

// ---------------------------------------------------------------------------
// launch
// ---------------------------------------------------------------------------
extern "C" void kernel_launch(void* const* d_in, const int* in_sizes, int n_in,
                              void* d_out, int out_size) {
    const float* x  = (const float*)d_in[0];
    const float* e  = (const float*)d_in[1];
    const void*  ei = d_in[2];
    const float* W0 = (const float*)d_in[3];
    const float* b0 = (const float*)d_in[4];
    const float* Wh = (const float*)d_in[5];
    const float* bh = (const float*)d_in[6];
    const float* Wo = (const float*)d_in[7];
    const float* bo = (const float*)d_in[8];
    const float* gw = (const float*)d_in[9];
    const float* gb = (const float*)d_in[10];
    float* out = (float*)d_out;

    float4 *msg, *h0, *h1;
    cudaGetSymbolAddress((void**)&msg, g_msg);
    cudaGetSymbolAddress((void**)&h0,  g_h0);
    cudaGetSymbolAddress((void**)&h1,  g_h1);

    const int smemB = 2 * 129 * 128 * 4;   // 132096 B
    cudaFuncSetAttribute(gemm2_kernel<2, true,  false>, cudaFuncAttributeMaxDynamicSharedMemorySize, smemB);
    cudaFuncSetAttribute(gemm2_kernel<1, true,  false>, cudaFuncAttributeMaxDynamicSharedMemorySize, smemB);
    cudaFuncSetAttribute(gemm2_kernel<1, false, true >, cudaFuncAttributeMaxDynamicSharedMemorySize, smemB);

    // 0) detect edge_index dtype
    detect_kernel<<<1, 32>>>(ei);
    // 1) zero msg
    zero_kernel<<<(N_NODES * DIM / 4 + 255) / 256, 256>>>(msg, N_NODES * DIM / 4);
    // 2) scatter-sum edges -> msg (dst row at offset N_EDGES)
    scatter_kernel<<<N_EDGES / 8, 256>>>((const float4*)e, ei, msg);

    const int gblocks = (N_NODES + 127) / 128;   // 782
    // 3) layer 0: relu([x, msg] @ W0 + b0)
    gemm2_kernel<2, true, false><<<gblocks, 512, smemB>>>(
        x, (const float*)msg, W0, b0, nullptr, nullptr, nullptr, (float*)h0, N_NODES);
    // 4) hidden layers
    gemm2_kernel<1, true, false><<<gblocks, 512, smemB>>>(
        (const float*)h0, nullptr, Wh, bh, nullptr, nullptr, nullptr, (float*)h1, N_NODES);
    gemm2_kernel<1, true, false><<<gblocks, 512, smemB>>>(
        (const float*)h1, nullptr, Wh + 128 * 128, bh + 128, nullptr, nullptr, nullptr, (float*)h0, N_NODES);
    // 5) output layer + fused GroupNorm + residual
    gemm2_kernel<1, false, true><<<gblocks, 512, smemB>>>(
        (const float*)h0, nullptr, Wo, bo, x, gw, gb, out, N_NODES);
}

// round 5
// speedup vs baseline: 1.7221x; 1.2081x over previous
#include <cuda_runtime.h>
#include <cuda_bf16.h>
#include <mma.h>
#include <cstdint>

using namespace nvcuda;

#define N_NODES 100000
#define N_EDGES 1600000

// ---------------------------------------------------------------------------
// Device scratch (allocation-free rules)
// ---------------------------------------------------------------------------
__device__ float4        g_msg[(size_t)N_NODES * 32];           // 51.2 MB
__device__ __nv_bfloat16 g_ahi[(size_t)N_NODES * 128];
__device__ __nv_bfloat16 g_alo[(size_t)N_NODES * 128];
__device__ __nv_bfloat16 g_bhi[(size_t)N_NODES * 128];
__device__ __nv_bfloat16 g_blo[(size_t)N_NODES * 128];
__device__ __nv_bfloat16 g_whi[5 * 128 * 128];                  // W^T split planes [chunk][n][k]
__device__ __nv_bfloat16 g_wlo[5 * 128 * 128];
__device__ int           g_mode;

// ---------------------------------------------------------------------------
// detect edge_index dtype
// ---------------------------------------------------------------------------
__global__ void detect_kernel(const void* eiv) {
    if (threadIdx.x != 0 || blockIdx.x != 0) return;
    const long long* e64 = (const long long*)eiv;
    const int*       e32 = (const int*)eiv;
    const float*     ef  = (const float*)eiv;
    bool ok64 = true, ok32 = true, okf = true;
    for (int i = 0; i < 32; i++) {
        long long v = e64[i];
        if (v < 0 || v >= N_NODES) ok64 = false;
        int w = e32[i];
        if (w < 0 || w >= N_NODES) ok32 = false;
        float f = ef[i];
        if (!(f >= 0.f && f < (float)N_NODES)) okf = false;
    }
    g_mode = ok64 ? 1 : (ok32 ? 0 : (okf ? 2 : 0));
}

__global__ void zero_kernel(float4* __restrict__ p, int n4) {
    int i = blockIdx.x * blockDim.x + threadIdx.x;
    if (i < n4) p[i] = make_float4(0.f, 0.f, 0.f, 0.f);
}

// ---------------------------------------------------------------------------
// scatter-sum: one warp per edge, lane handles 4 channels, vector RED to L2
// ---------------------------------------------------------------------------
__global__ void scatter_kernel(const float4* __restrict__ e4,
                               const void* __restrict__ eiv,
                               float4* __restrict__ msg) {
    __shared__ int mode;
    if (threadIdx.x == 0) mode = g_mode;
    __syncthreads();
    int warp = (blockIdx.x * blockDim.x + threadIdx.x) >> 5;
    int lane = threadIdx.x & 31;
    if (warp >= N_EDGES) return;
    int d;
    if (mode == 1)      d = (int)((const long long*)eiv)[N_EDGES + warp];
    else if (mode == 0) d = ((const int*)eiv)[N_EDGES + warp];
    else                d = (int)((const float*)eiv)[N_EDGES + warp];
    d = min(max(d, 0), N_NODES - 1);
    float4 v = e4[(size_t)warp * 32 + lane];
    float4* p = &msg[(size_t)d * 32 + lane];
    asm volatile("red.global.add.v4.f32 [%0], {%1,%2,%3,%4};"
                 :: "l"(p), "f"(v.x), "f"(v.y), "f"(v.z), "f"(v.w) : "memory");
}

// ---------------------------------------------------------------------------
// weight prep: transpose to [n][k], split into bf16 hi/lo
// chunk 0,1 = W0 (k 0-127 / 128-255); 2,3 = Wh[0],Wh[1]; 4 = Wo
// ---------------------------------------------------------------------------
__global__ void prep_kernel(const float* __restrict__ W0,
                            const float* __restrict__ Wh,
                            const float* __restrict__ Wo) {
    int i = blockIdx.x * 256 + threadIdx.x;
    if (i >= 5 * 128 * 128) return;
    int chunk = i >> 14;
    int r = i & 16383;
    int n = r >> 7, k = r & 127;
    float v;
    if (chunk < 2)      v = W0[(chunk * 128 + k) * 128 + n];
    else if (chunk < 4) v = Wh[(chunk - 2) * 16384 + k * 128 + n];
    else                v = Wo[k * 128 + n];
    __nv_bfloat16 h = __float2bfloat16(v);
    __nv_bfloat16 l = __float2bfloat16(v - __bfloat162float(h));
    g_whi[i] = h;
    g_wlo[i] = l;
}

// ---------------------------------------------------------------------------
// HMMA split-bf16 GEMM layer kernel: 256 threads, tile 128 rows x 128 cols.
// smem planes (bf16, stride 136): Ahi | Alo | Whi^T | Wlo^T.
// Epilogue spills acc to fp32 smem (reusing A planes), then bias/relu and
// either bf16 hi/lo plane output, or fused GroupNorm + residual fp32 output.
// ---------------------------------------------------------------------------
#define SSTR 136                       // bf16 elements per smem row
#define SA_HI 0
#define SA_LO (128 * SSTR * 2)         // 34816
#define SW_HI (2 * 128 * SSTR * 2)     // 69632
#define SW_LO (3 * 128 * SSTR * 2)     // 104448
#define SMEM_T (4 * 128 * SSTR * 2)    // 139264
#define CSTR 132                       // fp32 elements per C row (reuses SA region)

template<int NCHUNK, bool FP32SRC, bool RELU, bool NORM>
__global__ void __launch_bounds__(256, 1)
wgemm_kernel(const float* __restrict__ A1f, const float* __restrict__ A2f,
             const __nv_bfloat16* __restrict__ Ahi_g, const __nv_bfloat16* __restrict__ Alo_g,
             const __nv_bfloat16* __restrict__ Whi_g, const __nv_bfloat16* __restrict__ Wlo_g,
             const float* __restrict__ bias,
             const float* __restrict__ xres, const float* __restrict__ gw,
             const float* __restrict__ gb,
             float* __restrict__ outf,
             __nv_bfloat16* __restrict__ Ohi, __nv_bfloat16* __restrict__ Olo,
             int nrows) {
    extern __shared__ char smem[];
    const int tid = threadIdx.x, wid = tid >> 5;
    const int row0 = blockIdx.x * 128;
    const int wy = wid >> 1;           // 0..3 : rows wy*32..+31
    const int wx = wid & 1;            // 0..1 : cols wx*64..+63

    wmma::fragment<wmma::accumulator, 16, 16, 16, float> acc[2][4];
    #pragma unroll
    for (int i = 0; i < 2; i++)
        #pragma unroll
        for (int j = 0; j < 4; j++) wmma::fill_fragment(acc[i][j], 0.f);

    #pragma unroll
    for (int c = 0; c < NCHUNK; c++) {
        // ---- stage W chunk: [n][k] planes, 2048 uint4 each ----
        {
            const uint4* wh = (const uint4*)(Whi_g + c * 16384);
            const uint4* wl = (const uint4*)(Wlo_g + c * 16384);
            #pragma unroll
            for (int it = 0; it < 8; it++) {
                int i = tid + it * 256;
                int n = i >> 4, c16 = i & 15;
                uint32_t dst = n * (SSTR * 2) + c16 * 16;
                *(uint4*)(smem + SW_HI + dst) = wh[i];
                *(uint4*)(smem + SW_LO + dst) = wl[i];
            }
        }
        // ---- stage A chunk ----
        if (FP32SRC) {
            const float4* src = (const float4*)(c == 0 ? A1f : A2f);
            #pragma unroll
            for (int it = 0; it < 16; it++) {
                int i = tid + it * 256;          // 4096 float4
                int r = i >> 5, c4 = i & 31;
                int rg = row0 + r; if (rg >= nrows) rg = nrows - 1;
                float4 v = src[(size_t)rg * 32 + c4];
                __nv_bfloat16 h0 = __float2bfloat16(v.x), h1 = __float2bfloat16(v.y);
                __nv_bfloat16 h2 = __float2bfloat16(v.z), h3 = __float2bfloat16(v.w);
                __nv_bfloat16 l0 = __float2bfloat16(v.x - __bfloat162float(h0));
                __nv_bfloat16 l1 = __float2bfloat16(v.y - __bfloat162float(h1));
                __nv_bfloat16 l2 = __float2bfloat16(v.z - __bfloat162float(h2));
                __nv_bfloat16 l3 = __float2bfloat16(v.w - __bfloat162float(h3));
                uint2 hp, lp;
                hp.x = (uint32_t)__bfloat16_as_ushort(h0) | ((uint32_t)__bfloat16_as_ushort(h1) << 16);
                hp.y = (uint32_t)__bfloat16_as_ushort(h2) | ((uint32_t)__bfloat16_as_ushort(h3) << 16);
                lp.x = (uint32_t)__bfloat16_as_ushort(l0) | ((uint32_t)__bfloat16_as_ushort(l1) << 16);
                lp.y = (uint32_t)__bfloat16_as_ushort(l2) | ((uint32_t)__bfloat16_as_ushort(l3) << 16);
                uint32_t dst = r * (SSTR * 2) + c4 * 8;
                *(uint2*)(smem + SA_HI + dst) = hp;
                *(uint2*)(smem + SA_LO + dst) = lp;
            }
        } else {
            #pragma unroll
            for (int it = 0; it < 8; it++) {
                int i = tid + it * 256;          // 2048 uint4
                int r = i >> 4, c16 = i & 15;
                int rg = row0 + r; if (rg >= nrows) rg = nrows - 1;
                uint4 vh = *(const uint4*)(Ahi_g + (size_t)rg * 128 + c16 * 8);
                uint4 vl = *(const uint4*)(Alo_g + (size_t)rg * 128 + c16 * 8);
                uint32_t dst = r * (SSTR * 2) + c16 * 16;
                *(uint4*)(smem + SA_HI + dst) = vh;
                *(uint4*)(smem + SA_LO + dst) = vl;
            }
        }
        __syncthreads();

        const __nv_bfloat16* Ah = (const __nv_bfloat16*)(smem + SA_HI);
        const __nv_bfloat16* Al = (const __nv_bfloat16*)(smem + SA_LO);
        const __nv_bfloat16* Wh = (const __nv_bfloat16*)(smem + SW_HI);
        const __nv_bfloat16* Wl = (const __nv_bfloat16*)(smem + SW_LO);

        #pragma unroll 1
        for (int ks = 0; ks < 8; ks++) {
            const int k0 = ks * 16;
            wmma::fragment<wmma::matrix_a, 16, 16, 16, __nv_bfloat16, wmma::row_major> ah[2], al[2];
            wmma::fragment<wmma::matrix_b, 16, 16, 16, __nv_bfloat16, wmma::col_major> bh[4], bl[4];
            #pragma unroll
            for (int i = 0; i < 2; i++)
                wmma::load_matrix_sync(ah[i], &Ah[(wy * 32 + i * 16) * SSTR + k0], SSTR);
            #pragma unroll
            for (int j = 0; j < 4; j++)
                wmma::load_matrix_sync(bh[j], &Wh[(wx * 64 + j * 16) * SSTR + k0], SSTR);
            #pragma unroll
            for (int i = 0; i < 2; i++)
                #pragma unroll
                for (int j = 0; j < 4; j++)
                    wmma::mma_sync(acc[i][j], ah[i], bh[j], acc[i][j]);
            #pragma unroll
            for (int j = 0; j < 4; j++)
                wmma::load_matrix_sync(bl[j], &Wl[(wx * 64 + j * 16) * SSTR + k0], SSTR);
            #pragma unroll
            for (int i = 0; i < 2; i++)
                #pragma unroll
                for (int j = 0; j < 4; j++)
                    wmma::mma_sync(acc[i][j], ah[i], bl[j], acc[i][j]);
            #pragma unroll
            for (int i = 0; i < 2; i++)
                wmma::load_matrix_sync(al[i], &Al[(wy * 32 + i * 16) * SSTR + k0], SSTR);
            #pragma unroll
            for (int i = 0; i < 2; i++)
                #pragma unroll
                for (int j = 0; j < 4; j++)
                    wmma::mma_sync(acc[i][j], al[i], bh[j], acc[i][j]);
        }
        __syncthreads();
    }

    // ---- spill accumulators to fp32 smem tile (reuses A planes) ----
    float* Cs = (float*)(smem + SA_HI);
    #pragma unroll
    for (int i = 0; i < 2; i++)
        #pragma unroll
        for (int j = 0; j < 4; j++)
            wmma::store_matrix_sync(&Cs[(wy * 32 + i * 16) * CSTR + wx * 64 + j * 16],
                                    acc[i][j], CSTR, wmma::mem_row_major);
    __syncthreads();

    // ---- epilogue: thread t -> row t>>1, cols (t&1)*64..+63 ----
    const int row  = tid >> 1;
    const int half = tid & 1;
    const int rg   = row0 + row;
    const bool valid = rg < nrows;
    const int c0 = half * 64;

    float v[64];
    #pragma unroll
    for (int q = 0; q < 16; q++) {
        float4 cc = *(const float4*)&Cs[row * CSTR + c0 + q * 4];
        float4 bb = __ldg((const float4*)bias + (c0 >> 2) + q);
        v[q * 4 + 0] = cc.x + bb.x;
        v[q * 4 + 1] = cc.y + bb.y;
        v[q * 4 + 2] = cc.z + bb.z;
        v[q * 4 + 3] = cc.w + bb.w;
    }
    if (RELU) {
        #pragma unroll
        for (int j = 0; j < 64; j++) v[j] = fmaxf(v[j], 0.f);
    }

    if (NORM) {
        float s = 0.f, ss = 0.f;
        #pragma unroll
        for (int j = 0; j < 64; j++) { s += v[j]; ss += v[j] * v[j]; }
        s  += __shfl_xor_sync(0xFFFFFFFFu, s,  1);
        ss += __shfl_xor_sync(0xFFFFFFFFu, ss, 1);
        float mu  = s * (1.f / 128.f);
        float var = ss * (1.f / 128.f) - mu * mu;
        float rs  = rsqrtf(var + 1e-5f);
        if (valid) {
            const float4* x4  = (const float4*)xres;
            const float4* gw4 = (const float4*)gw;
            const float4* gb4 = (const float4*)gb;
            float4* o4 = (float4*)outf;
            #pragma unroll
            for (int q = 0; q < 16; q++) {
                float4 xg = x4[(size_t)rg * 32 + (c0 >> 2) + q];
                float4 wv = __ldg(gw4 + (c0 >> 2) + q);
                float4 bv = __ldg(gb4 + (c0 >> 2) + q);
                float4 r4;
                r4.x = xg.x + (v[q * 4 + 0] - mu) * rs * wv.x + bv.x;
                r4.y = xg.y + (v[q * 4 + 1] - mu) * rs * wv.y + bv.y;
                r4.z = xg.z + (v[q * 4 + 2] - mu) * rs * wv.z + bv.z;
                r4.w = xg.w + (v[q * 4 + 3] - mu) * rs * wv.w + bv.w;
                o4[(size_t)rg * 32 + (c0 >> 2) + q] = r4;
            }
        }
    } else if (valid) {
        #pragma unroll
        for (int g = 0; g < 8; g++) {
            uint4 hp, lp;
            uint32_t* hu = (uint32_t*)&hp;
            uint32_t* lu = (uint32_t*)&lp;
            #pragma unroll
            for (int q = 0; q < 4; q++) {
                float a = v[g * 8 + q * 2], b = v[g * 8 + q * 2 + 1];
                __nv_bfloat16 ha = __float2bfloat16(a), hb = __float2bfloat16(b);
                __nv_bfloat16 la = __float2bfloat16(a - __bfloat162float(ha));
                __nv_bfloat16 lb = __float2bfloat16(b - __bfloat162float(hb));
                hu[q] = (uint32_t)__bfloat16_as_ushort(ha) | ((uint32_t)__bfloat16_as_ushort(hb) << 16);
                lu[q] = (uint32_t)__bfloat16_as_ushort(la) | ((uint32_t)__bfloat16_as_ushort(lb) << 16);
            }
            ((uint4*)Ohi)[(size_t)rg * 16 + (c0 >> 3) + g] = hp;
            ((uint4*)Olo)[(size_t)rg * 16 + (c0 >> 3) + g] = lp;
        }
    }
}

// ---------------------------------------------------------------------------
// launch
// ---------------------------------------------------------------------------
extern "C" void kernel_launch(void* const* d_in, const int* in_sizes, int n_in,
                              void* d_out, int out_size) {
    const float* x  = (const float*)d_in[0];
    const float* e  = (const float*)d_in[1];
    const void*  ei = d_in[2];
    const float* W0 = (const float*)d_in[3];
    const float* b0 = (const float*)d_in[4];
    const float* Wh = (const float*)d_in[5];
    const float* bh = (const float*)d_in[6];
    const float* Wo = (const float*)d_in[7];
    const float* bo = (const float*)d_in[8];
    const float* gw = (const float*)d_in[9];
    const float* gb = (const float*)d_in[10];
    float* out = (float*)d_out;

    float4* msg;
    __nv_bfloat16 *ahi, *alo, *bhi, *blo, *whi, *wlo;
    cudaGetSymbolAddress((void**)&msg, g_msg);
    cudaGetSymbolAddress((void**)&ahi, g_ahi);
    cudaGetSymbolAddress((void**)&alo, g_alo);
    cudaGetSymbolAddress((void**)&bhi, g_bhi);
    cudaGetSymbolAddress((void**)&blo, g_blo);
    cudaGetSymbolAddress((void**)&whi, g_whi);
    cudaGetSymbolAddress((void**)&wlo, g_wlo);

    cudaFuncSetAttribute(wgemm_kernel<2, true,  true,  false>, cudaFuncAttributeMaxDynamicSharedMemorySize, SMEM_T);
    cudaFuncSetAttribute(wgemm_kernel<1, false, true,  false>, cudaFuncAttributeMaxDynamicSharedMemorySize, SMEM_T);
    cudaFuncSetAttribute(wgemm_kernel<1, false, false, true >, cudaFuncAttributeMaxDynamicSharedMemorySize, SMEM_T);

    detect_kernel<<<1, 32>>>(ei);
    zero_kernel<<<(N_NODES * 32 + 255) / 256, 256>>>(msg, N_NODES * 32);
    scatter_kernel<<<N_EDGES / 8, 256>>>((const float4*)e, ei, msg);
    prep_kernel<<<(5 * 128 * 128 + 255) / 256, 256>>>(W0, Wh, Wo);

    const int gblocks = (N_NODES + 127) / 128;   // 782
    // layer 0: relu([x | msg] @ W0 + b0)  -> a planes
    wgemm_kernel<2, true, true, false><<<gblocks, 256, SMEM_T>>>(
        x, (const float*)msg, nullptr, nullptr, whi, wlo, b0,
        nullptr, nullptr, nullptr, nullptr, ahi, alo, N_NODES);
    // hidden 1: a -> b
    wgemm_kernel<1, false, true, false><<<gblocks, 256, SMEM_T>>>(
        nullptr, nullptr, ahi, alo, whi + 2 * 16384, wlo + 2 * 16384, bh,
        nullptr, nullptr, nullptr, nullptr, bhi, blo, N_NODES);
    // hidden 2: b -> a
    wgemm_kernel<1, false, true, false><<<gblocks, 256, SMEM_T>>>(
        nullptr, nullptr, bhi, blo, whi + 3 * 16384, wlo + 3 * 16384, bh + 128,
        nullptr, nullptr, nullptr, nullptr, ahi, alo, N_NODES);
    // output + GroupNorm + residual: a -> out
    wgemm_kernel<1, false, false, true><<<gblocks, 256, SMEM_T>>>(
        nullptr, nullptr, ahi, alo, whi + 4 * 16384, wlo + 4 * 16384, bo,
        x, gw, gb, out, nullptr, nullptr, N_NODES);
}

// round 7
// speedup vs baseline: 1.9446x; 1.1292x over previous
#include <cuda_runtime.h>
#include <cuda_bf16.h>
#include <mma.h>
#include <cstdint>

using namespace nvcuda;

#define N_NODES 100000
#define N_EDGES 1600000

// ---------------------------------------------------------------------------
// Device scratch
// ---------------------------------------------------------------------------
__device__ float4        g_msg[(size_t)N_NODES * 32];   // 51.2 MB
__device__ __nv_bfloat16 g_whi[5 * 128 * 128];          // W^T split planes [chunk][n][k]
__device__ __nv_bfloat16 g_wlo[5 * 128 * 128];
__device__ int           g_mode;

// ---------------------------------------------------------------------------
// detect edge_index dtype
// ---------------------------------------------------------------------------
__global__ void detect_kernel(const void* eiv) {
    if (threadIdx.x != 0 || blockIdx.x != 0) return;
    const long long* e64 = (const long long*)eiv;
    const int*       e32 = (const int*)eiv;
    const float*     ef  = (const float*)eiv;
    bool ok64 = true, ok32 = true, okf = true;
    for (int i = 0; i < 32; i++) {
        long long v = e64[i];
        if (v < 0 || v >= N_NODES) ok64 = false;
        int w = e32[i];
        if (w < 0 || w >= N_NODES) ok32 = false;
        float f = ef[i];
        if (!(f >= 0.f && f < (float)N_NODES)) okf = false;
    }
    g_mode = ok64 ? 1 : (ok32 ? 0 : (okf ? 2 : 0));
}

__global__ void zero_kernel(float4* __restrict__ p, int n4) {
    int i = blockIdx.x * blockDim.x + threadIdx.x;
    if (i < n4) p[i] = make_float4(0.f, 0.f, 0.f, 0.f);
}

// ---------------------------------------------------------------------------
// scatter-sum: one warp per edge, lane handles 4 channels, vector RED to L2
// ---------------------------------------------------------------------------
__global__ void scatter_kernel(const float4* __restrict__ e4,
                               const void* __restrict__ eiv,
                               float4* __restrict__ msg) {
    __shared__ int mode;
    if (threadIdx.x == 0) mode = g_mode;
    __syncthreads();
    int warp = (blockIdx.x * blockDim.x + threadIdx.x) >> 5;
    int lane = threadIdx.x & 31;
    if (warp >= N_EDGES) return;
    int d;
    if (mode == 1)      d = (int)((const long long*)eiv)[N_EDGES + warp];
    else if (mode == 0) d = ((const int*)eiv)[N_EDGES + warp];
    else                d = (int)((const float*)eiv)[N_EDGES + warp];
    d = min(max(d, 0), N_NODES - 1);
    float4 v = e4[(size_t)warp * 32 + lane];
    float4* p = &msg[(size_t)d * 32 + lane];
    asm volatile("red.global.add.v4.f32 [%0], {%1,%2,%3,%4};"
                 :: "l"(p), "f"(v.x), "f"(v.y), "f"(v.z), "f"(v.w) : "memory");
}

// ---------------------------------------------------------------------------
// weight prep: transpose to [n][k], split into bf16 hi/lo
// chunk 0,1 = W0 (k 0-127 / 128-255); 2,3 = Wh[0],Wh[1]; 4 = Wo
// ---------------------------------------------------------------------------
__global__ void prep_kernel(const float* __restrict__ W0,
                            const float* __restrict__ Wh,
                            const float* __restrict__ Wo) {
    int i = blockIdx.x * 256 + threadIdx.x;
    if (i >= 5 * 128 * 128) return;
    int chunk = i >> 14;
    int r = i & 16383;
    int n = r >> 7, k = r & 127;
    float v;
    if (chunk < 2)      v = W0[(chunk * 128 + k) * 128 + n];
    else if (chunk < 4) v = Wh[(chunk - 2) * 16384 + k * 128 + n];
    else                v = Wo[k * 128 + n];
    __nv_bfloat16 h = __float2bfloat16(v);
    __nv_bfloat16 l = __float2bfloat16(v - __bfloat162float(h));
    g_whi[i] = h;
    g_wlo[i] = l;
}

// ---------------------------------------------------------------------------
// Fused 4-layer MLP kernel: one CTA per 128-row tile, activations never
// leave the SM between layers. 256 threads, 8 warps in 4x2 (wy,wx) grid.
// smem bf16 planes (stride 136): Ahi | Alo | Whi^T | Wlo^T. C spill region
// (fp32, stride 132) aliases the A planes.
// ---------------------------------------------------------------------------
#define SSTR 136
#define SB   (SSTR * 2)                 // 272 bytes per plane row
#define SA_HI 0
#define SA_LO (128 * SB)                // 34816
#define SW_HI (2 * 128 * SB)            // 69632
#define SW_LO (3 * 128 * SB)            // 104448
#define SMEM_T (4 * 128 * SB)           // 139264
#define CSTR 132

__device__ __forceinline__ void stage_w(char* smem,
                                        const __nv_bfloat16* __restrict__ Whi_g,
                                        const __nv_bfloat16* __restrict__ Wlo_g,
                                        int chunk, int tid) {
    const uint4* wh = (const uint4*)(Whi_g + chunk * 16384);
    const uint4* wl = (const uint4*)(Wlo_g + chunk * 16384);
    #pragma unroll
    for (int it = 0; it < 8; it++) {
        int i = tid + it * 256;         // 2048 x 16B per plane
        int n = i >> 4, c16 = i & 15;
        uint32_t dst = n * SB + c16 * 16;
        *(uint4*)(smem + SW_HI + dst) = wh[i];
        *(uint4*)(smem + SW_LO + dst) = wl[i];
    }
}

__device__ __forceinline__ void mma_tile(
    wmma::fragment<wmma::accumulator, 16, 16, 16, float> (&acc)[2][4],
    const char* smem, int wy, int wx) {
    const __nv_bfloat16* Ah = (const __nv_bfloat16*)(smem + SA_HI);
    const __nv_bfloat16* Al = (const __nv_bfloat16*)(smem + SA_LO);
    const __nv_bfloat16* Wh = (const __nv_bfloat16*)(smem + SW_HI);
    const __nv_bfloat16* Wl = (const __nv_bfloat16*)(smem + SW_LO);
    #pragma unroll 1
    for (int ks = 0; ks < 8; ks++) {
        const int k0 = ks * 16;
        wmma::fragment<wmma::matrix_a, 16, 16, 16, __nv_bfloat16, wmma::row_major> ah[2], al[2];
        wmma::fragment<wmma::matrix_b, 16, 16, 16, __nv_bfloat16, wmma::col_major> bh[4], bl[4];
        #pragma unroll
        for (int i = 0; i < 2; i++)
            wmma::load_matrix_sync(ah[i], &Ah[(wy * 32 + i * 16) * SSTR + k0], SSTR);
        #pragma unroll
        for (int j = 0; j < 4; j++)
            wmma::load_matrix_sync(bh[j], &Wh[(wx * 64 + j * 16) * SSTR + k0], SSTR);
        #pragma unroll
        for (int i = 0; i < 2; i++)
            #pragma unroll
            for (int j = 0; j < 4; j++)
                wmma::mma_sync(acc[i][j], ah[i], bh[j], acc[i][j]);
        #pragma unroll
        for (int j = 0; j < 4; j++)
            wmma::load_matrix_sync(bl[j], &Wl[(wx * 64 + j * 16) * SSTR + k0], SSTR);
        #pragma unroll
        for (int i = 0; i < 2; i++)
            #pragma unroll
            for (int j = 0; j < 4; j++)
                wmma::mma_sync(acc[i][j], ah[i], bl[j], acc[i][j]);
        #pragma unroll
        for (int i = 0; i < 2; i++)
            wmma::load_matrix_sync(al[i], &Al[(wy * 32 + i * 16) * SSTR + k0], SSTR);
        #pragma unroll
        for (int i = 0; i < 2; i++)
            #pragma unroll
            for (int j = 0; j < 4; j++)
                wmma::mma_sync(acc[i][j], al[i], bh[j], acc[i][j]);
    }
}

__device__ __forceinline__ void spill_acc(
    wmma::fragment<wmma::accumulator, 16, 16, 16, float> (&acc)[2][4],
    char* smem, int wy, int wx) {
    float* Cs = (float*)(smem + SA_HI);
    #pragma unroll
    for (int i = 0; i < 2; i++)
        #pragma unroll
        for (int j = 0; j < 4; j++)
            wmma::store_matrix_sync(&Cs[(wy * 32 + i * 16) * CSTR + wx * 64 + j * 16],
                                    acc[i][j], CSTR, wmma::mem_row_major);
}

// read one thread's 64 C values + bias (+relu)
__device__ __forceinline__ void load_v(const char* smem, const float* __restrict__ bias,
                                       int row, int c0, bool relu, float (&v)[64]) {
    const float* Cs = (const float*)(smem + SA_HI);
    #pragma unroll
    for (int q = 0; q < 16; q++) {
        float4 cc = *(const float4*)&Cs[row * CSTR + c0 + q * 4];
        float4 bb = __ldg((const float4*)bias + (c0 >> 2) + q);
        v[q * 4 + 0] = cc.x + bb.x;
        v[q * 4 + 1] = cc.y + bb.y;
        v[q * 4 + 2] = cc.z + bb.z;
        v[q * 4 + 3] = cc.w + bb.w;
    }
    if (relu) {
        #pragma unroll
        for (int j = 0; j < 64; j++) v[j] = fmaxf(v[j], 0.f);
    }
}

// write one thread's 64 values into the bf16 hi/lo A planes
// 8 groups x 8 elements; 8 bf16 = 16 bytes = one uint4 per plane per group
__device__ __forceinline__ void store_planes(char* smem, int row, int c0,
                                             const float (&v)[64]) {
    #pragma unroll
    for (int g = 0; g < 8; g++) {
        uint4 hp, lp;
        uint32_t* hu = (uint32_t*)&hp;
        uint32_t* lu = (uint32_t*)&lp;
        #pragma unroll
        for (int q = 0; q < 4; q++) {
            float a = v[g * 8 + q * 2], b = v[g * 8 + q * 2 + 1];
            __nv_bfloat16 ha = __float2bfloat16(a), hb = __float2bfloat16(b);
            __nv_bfloat16 la = __float2bfloat16(a - __bfloat162float(ha));
            __nv_bfloat16 lb = __float2bfloat16(b - __bfloat162float(hb));
            hu[q] = (uint32_t)__bfloat16_as_ushort(ha) | ((uint32_t)__bfloat16_as_ushort(hb) << 16);
            lu[q] = (uint32_t)__bfloat16_as_ushort(la) | ((uint32_t)__bfloat16_as_ushort(lb) << 16);
        }
        uint32_t dst = row * SB + (c0 + g * 8) * 2;
        *(uint4*)(smem + SA_HI + dst) = hp;
        *(uint4*)(smem + SA_LO + dst) = lp;
    }
}

__global__ void __launch_bounds__(256, 1)
fused_mlp_kernel(const float* __restrict__ x, const float* __restrict__ msgf,
                 const __nv_bfloat16* __restrict__ Whi_g, const __nv_bfloat16* __restrict__ Wlo_g,
                 const float* __restrict__ b0, const float* __restrict__ bh,
                 const float* __restrict__ bo,
                 const float* __restrict__ gw, const float* __restrict__ gb,
                 float* __restrict__ outf, int nrows) {
    extern __shared__ char smem[];
    const int tid = threadIdx.x, wid = tid >> 5;
    const int row0 = blockIdx.x * 128;
    const int wy = wid >> 1, wx = wid & 1;
    const int row  = tid >> 1;       // epilogue row (0..127)
    const int half = tid & 1;
    const int c0   = half * 64;
    const int rg   = row0 + row;
    const bool valid = rg < nrows;

    wmma::fragment<wmma::accumulator, 16, 16, 16, float> acc[2][4];
    float v[64];

    // ================= layer 0: relu([x | msg] @ W0 + b0) =================
    #pragma unroll
    for (int i = 0; i < 2; i++)
        #pragma unroll
        for (int j = 0; j < 4; j++) wmma::fill_fragment(acc[i][j], 0.f);

    #pragma unroll
    for (int c = 0; c < 2; c++) {
        stage_w(smem, Whi_g, Wlo_g, c, tid);
        const float4* src = (const float4*)(c == 0 ? x : msgf);
        #pragma unroll
        for (int it = 0; it < 16; it++) {
            int i = tid + it * 256;          // 4096 float4
            int r = i >> 5, c4 = i & 31;
            int rr = row0 + r; if (rr >= nrows) rr = nrows - 1;
            float4 w = src[(size_t)rr * 32 + c4];
            __nv_bfloat16 h0 = __float2bfloat16(w.x), h1 = __float2bfloat16(w.y);
            __nv_bfloat16 h2 = __float2bfloat16(w.z), h3 = __float2bfloat16(w.w);
            __nv_bfloat16 l0 = __float2bfloat16(w.x - __bfloat162float(h0));
            __nv_bfloat16 l1 = __float2bfloat16(w.y - __bfloat162float(h1));
            __nv_bfloat16 l2 = __float2bfloat16(w.z - __bfloat162float(h2));
            __nv_bfloat16 l3 = __float2bfloat16(w.w - __bfloat162float(h3));
            uint2 hp, lp;
            hp.x = (uint32_t)__bfloat16_as_ushort(h0) | ((uint32_t)__bfloat16_as_ushort(h1) << 16);
            hp.y = (uint32_t)__bfloat16_as_ushort(h2) | ((uint32_t)__bfloat16_as_ushort(h3) << 16);
            lp.x = (uint32_t)__bfloat16_as_ushort(l0) | ((uint32_t)__bfloat16_as_ushort(l1) << 16);
            lp.y = (uint32_t)__bfloat16_as_ushort(l2) | ((uint32_t)__bfloat16_as_ushort(l3) << 16);
            uint32_t dst = r * SB + c4 * 8;
            *(uint2*)(smem + SA_HI + dst) = hp;
            *(uint2*)(smem + SA_LO + dst) = lp;
        }
        __syncthreads();
        mma_tile(acc, smem, wy, wx);
        __syncthreads();
    }
    spill_acc(acc, smem, wy, wx);
    __syncthreads();
    load_v(smem, b0, row, c0, true, v);
    stage_w(smem, Whi_g, Wlo_g, 2, tid);     // next layer's W, overlapped
    __syncthreads();
    store_planes(smem, row, c0, v);
    __syncthreads();

    // ================= hidden layers 1,2 =================
    #pragma unroll
    for (int layer = 0; layer < 2; layer++) {
        #pragma unroll
        for (int i = 0; i < 2; i++)
            #pragma unroll
            for (int j = 0; j < 4; j++) wmma::fill_fragment(acc[i][j], 0.f);
        mma_tile(acc, smem, wy, wx);
        __syncthreads();
        spill_acc(acc, smem, wy, wx);
        __syncthreads();
        load_v(smem, bh + layer * 128, row, c0, true, v);
        stage_w(smem, Whi_g, Wlo_g, 3 + layer, tid);   // W for next stage
        __syncthreads();
        store_planes(smem, row, c0, v);
        __syncthreads();
    }

    // ================= output layer + GroupNorm + residual =================
    #pragma unroll
    for (int i = 0; i < 2; i++)
        #pragma unroll
        for (int j = 0; j < 4; j++) wmma::fill_fragment(acc[i][j], 0.f);
    mma_tile(acc, smem, wy, wx);
    __syncthreads();
    spill_acc(acc, smem, wy, wx);
    __syncthreads();
    load_v(smem, bo, row, c0, false, v);

    float s = 0.f, ss = 0.f;
    #pragma unroll
    for (int j = 0; j < 64; j++) { s += v[j]; ss += v[j] * v[j]; }
    s  += __shfl_xor_sync(0xFFFFFFFFu, s,  1);
    ss += __shfl_xor_sync(0xFFFFFFFFu, ss, 1);
    float mu  = s * (1.f / 128.f);
    float var = ss * (1.f / 128.f) - mu * mu;
    float rs  = rsqrtf(var + 1e-5f);
    if (valid) {
        const float4* x4  = (const float4*)x;
        const float4* gw4 = (const float4*)gw;
        const float4* gb4 = (const float4*)gb;
        float4* o4 = (float4*)outf;
        #pragma unroll
        for (int q = 0; q < 16; q++) {
            float4 xg = x4[(size_t)rg * 32 + (c0 >> 2) + q];
            float4 wv = __ldg(gw4 + (c0 >> 2) + q);
            float4 bv = __ldg(gb4 + (c0 >> 2) + q);
            float4 r4;
            r4.x = xg.x + (v[q * 4 + 0] - mu) * rs * wv.x + bv.x;
            r4.y = xg.y + (v[q * 4 + 1] - mu) * rs * wv.y + bv.y;
            r4.z = xg.z + (v[q * 4 + 2] - mu) * rs * wv.z + bv.z;
            r4.w = xg.w + (v[q * 4 + 3] - mu) * rs * wv.w + bv.w;
            o4[(size_t)rg * 32 + (c0 >> 2) + q] = r4;
        }
    }
}

// ---------------------------------------------------------------------------
// launch
// ---------------------------------------------------------------------------
extern "C" void kernel_launch(void* const* d_in, const int* in_sizes, int n_in,
                              void* d_out, int out_size) {
    const float* x  = (const float*)d_in[0];
    const float* e  = (const float*)d_in[1];
    const void*  ei = d_in[2];
    const float* W0 = (const float*)d_in[3];
    const float* b0 = (const float*)d_in[4];
    const float* Wh = (const float*)d_in[5];
    const float* bh = (const float*)d_in[6];
    const float* Wo = (const float*)d_in[7];
    const float* bo = (const float*)d_in[8];
    const float* gw = (const float*)d_in[9];
    const float* gb = (const float*)d_in[10];
    float* out = (float*)d_out;

    float4* msg;
    __nv_bfloat16 *whi, *wlo;
    cudaGetSymbolAddress((void**)&msg, g_msg);
    cudaGetSymbolAddress((void**)&whi, g_whi);
    cudaGetSymbolAddress((void**)&wlo, g_wlo);

    cudaFuncSetAttribute(fused_mlp_kernel, cudaFuncAttributeMaxDynamicSharedMemorySize, SMEM_T);

    detect_kernel<<<1, 32>>>(ei);
    zero_kernel<<<(N_NODES * 32 + 255) / 256, 256>>>(msg, N_NODES * 32);
    scatter_kernel<<<N_EDGES / 8, 256>>>((const float4*)e, ei, msg);
    prep_kernel<<<(5 * 128 * 128 + 255) / 256, 256>>>(W0, Wh, Wo);

    const int gblocks = (N_NODES + 127) / 128;   // 782
    fused_mlp_kernel<<<gblocks, 256, SMEM_T>>>(
        x, (const float*)msg, whi, wlo, b0, bh, bo, gw, gb, out, N_NODES);
}

// round 8
// speedup vs baseline: 2.1258x; 1.0932x over previous
#include <cuda_runtime.h>
#include <cuda_fp16.h>
#include <mma.h>
#include <cstdint>

using namespace nvcuda;

#define N_NODES 100000
#define N_EDGES 1600000

// ---------------------------------------------------------------------------
// Device scratch
// ---------------------------------------------------------------------------
__device__ float4 g_msg[(size_t)N_NODES * 32];   // 51.2 MB
__device__ __half g_whi[5 * 128 * 128];          // W^T split planes [chunk][n][k]
__device__ __half g_wlo[5 * 128 * 128];
__device__ int    g_mode;

// ---------------------------------------------------------------------------
// detect edge_index dtype
// ---------------------------------------------------------------------------
__global__ void detect_kernel(const void* eiv) {
    if (threadIdx.x != 0 || blockIdx.x != 0) return;
    const long long* e64 = (const long long*)eiv;
    const int*       e32 = (const int*)eiv;
    const float*     ef  = (const float*)eiv;
    bool ok64 = true, ok32 = true, okf = true;
    for (int i = 0; i < 32; i++) {
        long long v = e64[i];
        if (v < 0 || v >= N_NODES) ok64 = false;
        int w = e32[i];
        if (w < 0 || w >= N_NODES) ok32 = false;
        float f = ef[i];
        if (!(f >= 0.f && f < (float)N_NODES)) okf = false;
    }
    g_mode = ok64 ? 1 : (ok32 ? 0 : (okf ? 2 : 0));
}

__global__ void zero_kernel(float4* __restrict__ p, int n4) {
    int i = blockIdx.x * blockDim.x + threadIdx.x;
    if (i < n4) p[i] = make_float4(0.f, 0.f, 0.f, 0.f);
}

// ---------------------------------------------------------------------------
// scatter-sum: one warp per edge, lane handles 4 channels, vector RED to L2
// ---------------------------------------------------------------------------
__global__ void scatter_kernel(const float4* __restrict__ e4,
                               const void* __restrict__ eiv,
                               float4* __restrict__ msg) {
    __shared__ int mode;
    if (threadIdx.x == 0) mode = g_mode;
    __syncthreads();
    int warp = (blockIdx.x * blockDim.x + threadIdx.x) >> 5;
    int lane = threadIdx.x & 31;
    if (warp >= N_EDGES) return;
    int d;
    if (mode == 1)      d = (int)((const long long*)eiv)[N_EDGES + warp];
    else if (mode == 0) d = ((const int*)eiv)[N_EDGES + warp];
    else                d = (int)((const float*)eiv)[N_EDGES + warp];
    d = min(max(d, 0), N_NODES - 1);
    float4 v = e4[(size_t)warp * 32 + lane];
    float4* p = &msg[(size_t)d * 32 + lane];
    asm volatile("red.global.add.v4.f32 [%0], {%1,%2,%3,%4};"
                 :: "l"(p), "f"(v.x), "f"(v.y), "f"(v.z), "f"(v.w) : "memory");
}

// ---------------------------------------------------------------------------
// weight prep: transpose to [n][k], split into fp16 hi/lo (hi+lo ~ exact W)
// chunk 0,1 = W0 (k 0-127 / 128-255); 2,3 = Wh[0],Wh[1]; 4 = Wo
// ---------------------------------------------------------------------------
__global__ void prep_kernel(const float* __restrict__ W0,
                            const float* __restrict__ Wh,
                            const float* __restrict__ Wo) {
    int i = blockIdx.x * 256 + threadIdx.x;
    if (i >= 5 * 128 * 128) return;
    int chunk = i >> 14;
    int r = i & 16383;
    int n = r >> 7, k = r & 127;
    float v;
    if (chunk < 2)      v = W0[(chunk * 128 + k) * 128 + n];
    else if (chunk < 4) v = Wh[(chunk - 2) * 16384 + k * 128 + n];
    else                v = Wo[k * 128 + n];
    __half h = __float2half_rn(v);
    __half l = __float2half_rn(v - __half2float(h));
    g_whi[i] = h;
    g_wlo[i] = l;
}

// ---------------------------------------------------------------------------
// Fused 4-layer MLP: one CTA per 128-row tile, 512 threads, 16 warps (4x4).
// Activations: single fp16 plane. Weights: fp16 hi/lo planes (split = exact).
// C = A*Whi + A*Wlo  -> 2 HMMA products per k-step.
// smem: A(fp16,stride 136) | Whi | Wlo | norm-red. C spill (fp32, stride 132)
// aliases A+Whi.
// ---------------------------------------------------------------------------
#define SSTR 136
#define SB   (SSTR * 2)                 // 272 B per plane row
#define SA   0
#define SWH  (128 * SB)                 // 34816
#define SWL  (2 * 128 * SB)             // 69632
#define SRED (3 * 128 * SB)             // 104448
#define SMEM_T (SRED + 2048 + 64)       // 106560
#define CSTR 132                        // fp32 C row stride (67584 B < SWL)

__device__ __forceinline__ void stage_w(char* smem,
                                        const __half* __restrict__ Whi_g,
                                        const __half* __restrict__ Wlo_g,
                                        int chunk, int tid) {
    const uint4* wh = (const uint4*)(Whi_g + chunk * 16384);
    const uint4* wl = (const uint4*)(Wlo_g + chunk * 16384);
    #pragma unroll
    for (int it = 0; it < 4; it++) {
        int i = tid + it * 512;          // 2048 x 16B per plane
        int n = i >> 4, c16 = i & 15;
        uint32_t dst = n * SB + c16 * 16;
        *(uint4*)(smem + SWH + dst) = wh[i];
        *(uint4*)(smem + SWL + dst) = wl[i];
    }
}

__device__ __forceinline__ void mma_tile(
    wmma::fragment<wmma::accumulator, 16, 16, 16, float> (&acc)[2][2],
    const char* smem, int wy, int wx) {
    const __half* Ah = (const __half*)(smem + SA);
    const __half* Wh = (const __half*)(smem + SWH);
    const __half* Wl = (const __half*)(smem + SWL);
    #pragma unroll 1
    for (int ks = 0; ks < 8; ks++) {
        const int k0 = ks * 16;
        wmma::fragment<wmma::matrix_a, 16, 16, 16, __half, wmma::row_major> af[2];
        wmma::fragment<wmma::matrix_b, 16, 16, 16, __half, wmma::col_major> bh[2], bl[2];
        #pragma unroll
        for (int i = 0; i < 2; i++)
            wmma::load_matrix_sync(af[i], &Ah[(wy * 32 + i * 16) * SSTR + k0], SSTR);
        #pragma unroll
        for (int j = 0; j < 2; j++)
            wmma::load_matrix_sync(bh[j], &Wh[(wx * 32 + j * 16) * SSTR + k0], SSTR);
        #pragma unroll
        for (int i = 0; i < 2; i++)
            #pragma unroll
            for (int j = 0; j < 2; j++)
                wmma::mma_sync(acc[i][j], af[i], bh[j], acc[i][j]);
        #pragma unroll
        for (int j = 0; j < 2; j++)
            wmma::load_matrix_sync(bl[j], &Wl[(wx * 32 + j * 16) * SSTR + k0], SSTR);
        #pragma unroll
        for (int i = 0; i < 2; i++)
            #pragma unroll
            for (int j = 0; j < 2; j++)
                wmma::mma_sync(acc[i][j], af[i], bl[j], acc[i][j]);
    }
}

__device__ __forceinline__ void zero_acc(
    wmma::fragment<wmma::accumulator, 16, 16, 16, float> (&acc)[2][2]) {
    #pragma unroll
    for (int i = 0; i < 2; i++)
        #pragma unroll
        for (int j = 0; j < 2; j++) wmma::fill_fragment(acc[i][j], 0.f);
}

__device__ __forceinline__ void spill_acc(
    wmma::fragment<wmma::accumulator, 16, 16, 16, float> (&acc)[2][2],
    char* smem, int wy, int wx) {
    float* Cs = (float*)(smem + SA);
    #pragma unroll
    for (int i = 0; i < 2; i++)
        #pragma unroll
        for (int j = 0; j < 2; j++)
            wmma::store_matrix_sync(&Cs[(wy * 32 + i * 16) * CSTR + wx * 32 + j * 16],
                                    acc[i][j], CSTR, wmma::mem_row_major);
}

// thread handles row=tid>>2, cols quad*32..+31 (quad = tid&3): 32 values
__device__ __forceinline__ void load_v(const char* smem, const float* __restrict__ bias,
                                       int row, int quad, bool relu, float (&v)[32]) {
    const float* Cs = (const float*)(smem + SA);
    #pragma unroll
    for (int q = 0; q < 8; q++) {
        float4 cc = *(const float4*)&Cs[row * CSTR + quad * 32 + q * 4];
        float4 bb = __ldg((const float4*)bias + quad * 8 + q);
        v[q * 4 + 0] = cc.x + bb.x;
        v[q * 4 + 1] = cc.y + bb.y;
        v[q * 4 + 2] = cc.z + bb.z;
        v[q * 4 + 3] = cc.w + bb.w;
    }
    if (relu) {
        #pragma unroll
        for (int j = 0; j < 32; j++) v[j] = fmaxf(v[j], 0.f);
    }
}

// write 32 fp16 activations (64 B = 4 uint4) into the A plane
__device__ __forceinline__ void store_a(char* smem, int row, int quad,
                                        const float (&v)[32]) {
    #pragma unroll
    for (int g = 0; g < 4; g++) {
        uint4 p;
        uint32_t* pu = (uint32_t*)&p;
        #pragma unroll
        for (int q = 0; q < 4; q++) {
            __half2 h2 = __floats2half2_rn(v[g * 8 + q * 2], v[g * 8 + q * 2 + 1]);
            pu[q] = *(uint32_t*)&h2;
        }
        *(uint4*)(smem + SA + row * SB + quad * 64 + g * 16) = p;
    }
}

__global__ void __launch_bounds__(512, 1)
fused_mlp_kernel(const float* __restrict__ x, const float* __restrict__ msgf,
                 const __half* __restrict__ Whi_g, const __half* __restrict__ Wlo_g,
                 const float* __restrict__ b0, const float* __restrict__ bh,
                 const float* __restrict__ bo,
                 const float* __restrict__ gw, const float* __restrict__ gb,
                 float* __restrict__ outf, int nrows) {
    extern __shared__ char smem[];
    const int tid = threadIdx.x, wid = tid >> 5;
    const int row0 = blockIdx.x * 128;
    const int wy = wid >> 2, wx = wid & 3;     // 4x4 warp grid, 32x32 each
    const int row  = tid >> 2;                 // epilogue row (0..127)
    const int quad = tid & 3;                  // column quarter
    const int rg   = row0 + row;
    const bool valid = rg < nrows;

    wmma::fragment<wmma::accumulator, 16, 16, 16, float> acc[2][2];
    float v[32];

    // ================= layer 0: relu([x | msg] @ W0 + b0) =================
    zero_acc(acc);
    #pragma unroll
    for (int c = 0; c < 2; c++) {
        stage_w(smem, Whi_g, Wlo_g, c, tid);
        const float4* src = (const float4*)(c == 0 ? x : msgf);
        #pragma unroll
        for (int it = 0; it < 8; it++) {
            int i = tid + it * 512;            // 4096 float4
            int r = i >> 5, c4 = i & 31;
            int rr = row0 + r; if (rr >= nrows) rr = nrows - 1;
            float4 w = src[(size_t)rr * 32 + c4];
            __half2 h0 = __floats2half2_rn(w.x, w.y);
            __half2 h1 = __floats2half2_rn(w.z, w.w);
            uint2 p;
            p.x = *(uint32_t*)&h0;
            p.y = *(uint32_t*)&h1;
            *(uint2*)(smem + SA + r * SB + c4 * 8) = p;
        }
        __syncthreads();
        mma_tile(acc, smem, wy, wx);
        __syncthreads();
    }
    spill_acc(acc, smem, wy, wx);
    __syncthreads();
    load_v(smem, b0, row, quad, true, v);
    __syncthreads();
    store_a(smem, row, quad, v);
    stage_w(smem, Whi_g, Wlo_g, 2, tid);       // next layer's W
    __syncthreads();

    // ================= hidden layers 1,2 =================
    #pragma unroll
    for (int layer = 0; layer < 2; layer++) {
        zero_acc(acc);
        mma_tile(acc, smem, wy, wx);
        __syncthreads();
        spill_acc(acc, smem, wy, wx);
        __syncthreads();
        load_v(smem, bh + layer * 128, row, quad, true, v);
        __syncthreads();
        store_a(smem, row, quad, v);
        stage_w(smem, Whi_g, Wlo_g, 3 + layer, tid);
        __syncthreads();
    }

    // ================= output layer + GroupNorm + residual =================
    zero_acc(acc);
    mma_tile(acc, smem, wy, wx);
    __syncthreads();
    spill_acc(acc, smem, wy, wx);
    __syncthreads();
    load_v(smem, bo, row, quad, false, v);

    float s = 0.f, ss = 0.f;
    #pragma unroll
    for (int j = 0; j < 32; j++) { s += v[j]; ss += v[j] * v[j]; }
    s  += __shfl_xor_sync(0xFFFFFFFFu, s,  1);
    ss += __shfl_xor_sync(0xFFFFFFFFu, ss, 1);
    s  += __shfl_xor_sync(0xFFFFFFFFu, s,  2);
    ss += __shfl_xor_sync(0xFFFFFFFFu, ss, 2);
    float mu  = s * (1.f / 128.f);
    float var = ss * (1.f / 128.f) - mu * mu;
    float rs  = rsqrtf(var + 1e-5f);
    if (valid) {
        const float4* x4  = (const float4*)x;
        const float4* gw4 = (const float4*)gw;
        const float4* gb4 = (const float4*)gb;
        float4* o4 = (float4*)outf;
        #pragma unroll
        for (int q = 0; q < 8; q++) {
            float4 xg = x4[(size_t)rg * 32 + quad * 8 + q];
            float4 wv = __ldg(gw4 + quad * 8 + q);
            float4 bv = __ldg(gb4 + quad * 8 + q);
            float4 r4;
            r4.x = xg.x + (v[q * 4 + 0] - mu) * rs * wv.x + bv.x;
            r4.y = xg.y + (v[q * 4 + 1] - mu) * rs * wv.y + bv.y;
            r4.z = xg.z + (v[q * 4 + 2] - mu) * rs * wv.z + bv.z;
            r4.w = xg.w + (v[q * 4 + 3] - mu) * rs * wv.w + bv.w;
            o4[(size_t)rg * 32 + quad * 8 + q] = r4;
        }
    }
}

// ---------------------------------------------------------------------------
// launch
// ---------------------------------------------------------------------------
extern "C" void kernel_launch(void* const* d_in, const int* in_sizes, int n_in,
                              void* d_out, int out_size) {
    const float* x  = (const float*)d_in[0];
    const float* e  = (const float*)d_in[1];
    const void*  ei = d_in[2];
    const float* W0 = (const float*)d_in[3];
    const float* b0 = (const float*)d_in[4];
    const float* Wh = (const float*)d_in[5];
    const float* bh = (const float*)d_in[6];
    const float* Wo = (const float*)d_in[7];
    const float* bo = (const float*)d_in[8];
    const float* gw = (const float*)d_in[9];
    const float* gb = (const float*)d_in[10];
    float* out = (float*)d_out;

    float4* msg;
    __half *whi, *wlo;
    cudaGetSymbolAddress((void**)&msg, g_msg);
    cudaGetSymbolAddress((void**)&whi, g_whi);
    cudaGetSymbolAddress((void**)&wlo, g_wlo);

    cudaFuncSetAttribute(fused_mlp_kernel, cudaFuncAttributeMaxDynamicSharedMemorySize, SMEM_T);

    detect_kernel<<<1, 32>>>(ei);
    zero_kernel<<<(N_NODES * 32 + 255) / 256, 256>>>(msg, N_NODES * 32);
    scatter_kernel<<<N_EDGES / 8, 256>>>((const float4*)e, ei, msg);
    prep_kernel<<<(5 * 128 * 128 + 255) / 256, 256>>>(W0, Wh, Wo);

    const int gblocks = (N_NODES + 127) / 128;   // 782
    fused_mlp_kernel<<<gblocks, 512, SMEM_T>>>(
        x, (const float*)msg, whi, wlo, b0, bh, bo, gw, gb, out, N_NODES);
}